// round 6
// baseline (speedup 1.0000x reference)
#include <cuda_runtime.h>
#include <math.h>

#define IN_DIM 768
#define KSEL   38
#define NF     76     // MLP_IN = 2*K
#define HID    256
#define ROWS   64
#define THREADS 256
#define KC     32

// ---- smem layout (float offsets) ----
#define OFF_XIN 0                    // [76][65]  = 4940
#define OFF_W   4940                 // weight buf: max(76*257, 256*81) = 20736
#define OFF_XS  4940                 // phase1 alias: [32][65] = 2080
#define OFF_BS  (4940 + 2080)        // phase1 alias: [32][81] = 2592
#define OFF_CS  4940                 // phase3 alias: [76][129] = 9804
#define OFF_HS  25676                // [64][257] = 16448
#define OFF_ZS  42124                // [76][65]  = 4940
#define SMEM_FLOATS 47064
#define SMEM_BYTES  (SMEM_FLOATS * 4)

// Precomputed DFT analysis/synthesis tables
__device__ float g_B[IN_DIM * NF];   // [n][k]  x_in = x @ B
__device__ float g_C[NF * IN_DIM];   // [k][n]  out  = z @ C

__global__ void precompute_tables(const int* __restrict__ indices) {
    int tid = blockIdx.x * blockDim.x + threadIdx.x;
    if (tid >= IN_DIM * NF) return;
    int n = tid / NF;
    int k = tid - n * NF;
    int f = indices[(k < KSEL) ? k : (k - KSEL)];
    long long m = ((long long)f * (long long)n) % IN_DIM;
    double th = (2.0 * 3.14159265358979323846 / (double)IN_DIM) * (double)m;
    double s, c;
    sincos(th, &s, &c);
    double bval = (k < KSEL) ? c : -s;
    // irfft weight: interior bins count twice (conjugate pair); DC/Nyquist once.
    double w = (f == 0 || 2 * f == IN_DIM) ? (1.0 / IN_DIM) : (2.0 / IN_DIM);
    g_B[n * NF + k] = (float)bval;
    g_C[k * IN_DIM + n] = (float)(w * bval);
}

__global__ __launch_bounds__(THREADS, 1)
void fused_kernel(const float* __restrict__ x,
                  const float* __restrict__ eps,
                  const float* __restrict__ mu_w1, const float* __restrict__ mu_b1,
                  const float* __restrict__ mu_g,  const float* __restrict__ mu_beta,
                  const float* __restrict__ mu_w2, const float* __restrict__ mu_b2,
                  const float* __restrict__ sg_w1, const float* __restrict__ sg_b1,
                  const float* __restrict__ sg_g,  const float* __restrict__ sg_beta,
                  const float* __restrict__ sg_w2, const float* __restrict__ sg_b2,
                  float* __restrict__ out)
{
    extern __shared__ float sm[];
    float* XIN = sm + OFF_XIN;   // [76][65] k-major features
    float* WB  = sm + OFF_W;
    float* XS  = sm + OFF_XS;    // [32][65]
    float* BS  = sm + OFF_BS;    // [32][81]
    float* CS  = sm + OFF_CS;    // [76][129]
    float* HS  = sm + OFF_HS;    // [64][257]
    float* ZS  = sm + OFF_ZS;    // [76][65]

    const int tid = threadIdx.x;
    const int tr = tid >> 4;      // 0..15 : owns rows tr, tr+16, tr+32, tr+48
    const int tc = tid & 15;      // 0..15 : owns cols tc + 16*l
    const int row0 = blockIdx.x * ROWS;

    // ================= Phase 1: XIN[64][76] = X[64][768] @ B =================
    float acc1[4][5];
    #pragma unroll
    for (int j = 0; j < 4; j++)
        #pragma unroll
        for (int l = 0; l < 5; l++) acc1[j][l] = 0.f;

    for (int kb = 0; kb < IN_DIM; kb += KC) {
        __syncthreads();
        {   // load 64 rows x 32 cols of x, store k-major transposed
            int r  = tid >> 3;          // 0..31
            int cc = (tid & 7) * 4;     // 0..28
            #pragma unroll
            for (int h = 0; h < 2; h++) {
                int rr = r + h * 32;
                float4 v = *reinterpret_cast<const float4*>(
                    &x[(size_t)(row0 + rr) * IN_DIM + kb + cc]);
                XS[(cc + 0) * 65 + rr] = v.x;
                XS[(cc + 1) * 65 + rr] = v.y;
                XS[(cc + 2) * 65 + rr] = v.z;
                XS[(cc + 3) * 65 + rr] = v.w;
            }
        }
        for (int idx = tid; idx < KC * NF; idx += THREADS) {
            int kk = idx / NF, c = idx - kk * NF;
            BS[kk * 81 + c] = g_B[(kb + kk) * NF + c];
        }
        __syncthreads();
        #pragma unroll
        for (int kk = 0; kk < KC; kk++) {
            float a[4], b[5];
            #pragma unroll
            for (int j = 0; j < 4; j++) a[j] = XS[kk * 65 + tr + 16 * j];
            #pragma unroll
            for (int l = 0; l < 5; l++) b[l] = BS[kk * 81 + tc + 16 * l];
            #pragma unroll
            for (int j = 0; j < 4; j++)
                #pragma unroll
                for (int l = 0; l < 5; l++)
                    acc1[j][l] = fmaf(a[j], b[l], acc1[j][l]);
        }
    }
    __syncthreads();
    #pragma unroll
    for (int j = 0; j < 4; j++)
        #pragma unroll
        for (int l = 0; l < 5; l++) {
            int c = tc + 16 * l;
            if (c < NF) XIN[c * 65 + tr + 16 * j] = acc1[j][l];
        }

    // ================= Phase 2: two MLPs (mu then sigma) =================
    float zmu[4][5];
    #pragma unroll 1
    for (int p = 0; p < 2; p++) {
        const float* w1 = p ? sg_w1 : mu_w1;
        const float* b1 = p ? sg_b1 : mu_b1;
        const float* gg = p ? sg_g  : mu_g;
        const float* bt = p ? sg_beta : mu_beta;
        const float* w2 = p ? sg_w2 : mu_w2;
        const float* b2 = p ? sg_b2 : mu_b2;

        __syncthreads();   // WB / HS safe to overwrite
        // stage W1^T: WB[i*257 + j] = w1[j][i]   (coalesced read)
        for (int idx = tid; idx < HID * NF; idx += THREADS) {
            int j = idx / NF, i = idx - j * NF;
            WB[i * 257 + j] = w1[idx];
        }
        __syncthreads();

        // H[64][256] = XIN @ W1^T
        float acc[4][16];
        #pragma unroll
        for (int j = 0; j < 4; j++)
            #pragma unroll
            for (int l = 0; l < 16; l++) acc[j][l] = 0.f;
        for (int i = 0; i < NF; i++) {
            float a[4], b[16];
            #pragma unroll
            for (int j = 0; j < 4; j++) a[j] = XIN[i * 65 + tr + 16 * j];
            #pragma unroll
            for (int l = 0; l < 16; l++) b[l] = WB[i * 257 + tc + 16 * l];
            #pragma unroll
            for (int j = 0; j < 4; j++)
                #pragma unroll
                for (int l = 0; l < 16; l++)
                    acc[j][l] = fmaf(a[j], b[l], acc[j][l]);
        }
        #pragma unroll
        for (int j = 0; j < 4; j++)
            #pragma unroll
            for (int l = 0; l < 16; l++)
                HS[(tr + 16 * j) * 257 + tc + 16 * l] = acc[j][l];
        __syncthreads();

        // stage W2^T: WB[k*81 + o] = w2[o][k]   (coalesced read)
        for (int idx = tid; idx < NF * HID; idx += THREADS) {
            int o = idx >> 8, k = idx & 255;
            WB[k * 81 + o] = w2[idx];
        }
        // LayerNorm + exact GELU: one warp per row, 8 rows per warp
        {
            int w = tid >> 5, lane = tid & 31;
            for (int rr = 0; rr < 8; rr++) {
                int row = w * 8 + rr;
                float v[8], s = 0.f, sq = 0.f;
                #pragma unroll
                for (int m = 0; m < 8; m++) {
                    int c = lane + 32 * m;
                    v[m] = HS[row * 257 + c] + b1[c];
                    s += v[m];
                    sq = fmaf(v[m], v[m], sq);
                }
                #pragma unroll
                for (int o = 16; o > 0; o >>= 1) {
                    s  += __shfl_xor_sync(0xffffffffu, s,  o);
                    sq += __shfl_xor_sync(0xffffffffu, sq, o);
                }
                float mean = s * (1.f / HID);
                float var  = sq * (1.f / HID) - mean * mean;
                float inv  = rsqrtf(var + 1e-5f);
                #pragma unroll
                for (int m = 0; m < 8; m++) {
                    int c = lane + 32 * m;
                    float hn = (v[m] - mean) * inv * gg[c] + bt[c];
                    float ge = 0.5f * hn * (1.f + erff(hn * 0.70710678118654752f));
                    HS[row * 257 + c] = ge;
                }
            }
        }
        __syncthreads();

        // Z[64][76] = gelu(H) @ W2^T
        float acc2[4][5];
        #pragma unroll
        for (int j = 0; j < 4; j++)
            #pragma unroll
            for (int l = 0; l < 5; l++) acc2[j][l] = 0.f;
        for (int k = 0; k < HID; k++) {
            float a[4], b[5];
            #pragma unroll
            for (int j = 0; j < 4; j++) a[j] = HS[(tr + 16 * j) * 257 + k];
            #pragma unroll
            for (int l = 0; l < 5; l++) b[l] = WB[k * 81 + tc + 16 * l];
            #pragma unroll
            for (int j = 0; j < 4; j++)
                #pragma unroll
                for (int l = 0; l < 5; l++)
                    acc2[j][l] = fmaf(a[j], b[l], acc2[j][l]);
        }
        if (p == 0) {
            #pragma unroll
            for (int j = 0; j < 4; j++)
                #pragma unroll
                for (int l = 0; l < 5; l++) {
                    int c = tc + 16 * l;
                    zmu[j][l] = acc2[j][l] + ((c < NF) ? b2[c] : 0.f);
                }
        } else {
            #pragma unroll
            for (int j = 0; j < 4; j++)
                #pragma unroll
                for (int l = 0; l < 5; l++) {
                    int c = tc + 16 * l;
                    if (c < NF) {
                        int r = tr + 16 * j;
                        float zs = acc2[j][l] + b2[c];
                        float z = fmaf(eps[(size_t)(row0 + r) * NF + c], zs, zmu[j][l]);
                        ZS[c * 65 + r] = z;
                    }
                }
        }
    }

    // ================= Phase 3: out[64][768] = Z @ C =================
    for (int nc = 0; nc < IN_DIM; nc += 128) {
        __syncthreads();
        for (int idx = tid; idx < NF * 128; idx += THREADS) {
            int k = idx >> 7, c = idx & 127;
            CS[k * 129 + c] = g_C[k * IN_DIM + nc + c];
        }
        __syncthreads();
        float acc3[4][8];
        #pragma unroll
        for (int j = 0; j < 4; j++)
            #pragma unroll
            for (int l = 0; l < 8; l++) acc3[j][l] = 0.f;
        for (int k = 0; k < NF; k++) {
            float a[4], b[8];
            #pragma unroll
            for (int j = 0; j < 4; j++) a[j] = ZS[k * 65 + tr + 16 * j];
            #pragma unroll
            for (int l = 0; l < 8; l++) b[l] = CS[k * 129 + tc + 16 * l];
            #pragma unroll
            for (int j = 0; j < 4; j++)
                #pragma unroll
                for (int l = 0; l < 8; l++)
                    acc3[j][l] = fmaf(a[j], b[l], acc3[j][l]);
        }
        #pragma unroll
        for (int j = 0; j < 4; j++)
            #pragma unroll
            for (int l = 0; l < 8; l++)
                out[(size_t)(row0 + tr + 16 * j) * IN_DIM + nc + tc + 16 * l] = acc3[j][l];
    }
}

extern "C" void kernel_launch(void* const* d_in, const int* in_sizes, int n_in,
                              void* d_out, int out_size) {
    const float* x       = (const float*)d_in[0];
    const float* eps     = (const float*)d_in[1];
    const int*   indices = (const int*)  d_in[2];
    const float* mu_w1   = (const float*)d_in[3];
    const float* mu_b1   = (const float*)d_in[4];
    const float* mu_g    = (const float*)d_in[5];
    const float* mu_beta = (const float*)d_in[6];
    const float* mu_w2   = (const float*)d_in[7];
    const float* mu_b2   = (const float*)d_in[8];
    const float* sg_w1   = (const float*)d_in[9];
    const float* sg_b1   = (const float*)d_in[10];
    const float* sg_g    = (const float*)d_in[11];
    const float* sg_beta = (const float*)d_in[12];
    const float* sg_w2   = (const float*)d_in[13];
    const float* sg_b2   = (const float*)d_in[14];
    float* out = (float*)d_out;

    int n_rows = in_sizes[0] / IN_DIM;   // 32768

    cudaFuncSetAttribute(fused_kernel,
                         cudaFuncAttributeMaxDynamicSharedMemorySize, SMEM_BYTES);

    precompute_tables<<<(IN_DIM * NF + 255) / 256, 256>>>(indices);

    fused_kernel<<<n_rows / ROWS, THREADS, SMEM_BYTES>>>(
        x, eps,
        mu_w1, mu_b1, mu_g, mu_beta, mu_w2, mu_b2,
        sg_w1, sg_b1, sg_g, sg_beta, sg_w2, sg_b2,
        out);
}

// round 7
// speedup vs baseline: 1.8004x; 1.8004x over previous
#include <cuda_runtime.h>
#include <math.h>

#define IN_DIM 768
#define KSEL   38
#define NF     76     // MLP_IN
#define NFP    80     // padded to multiple of 16
#define HID    256
#define ROWS   64
#define THREADS 512

// shared-memory strides (floats)
#define SR   68       // [.][row] buffers: 68*4B = 272B = 17*16 (float4-aligned, bank-skewed)
#define W1S  260      // W1^T rows
#define W2S  84       // W2^T rows
#define CSS  132      // C tile rows
#define BSS  84       // B tile rows

// smem layout (float offsets)
#define OFF_XIN 0                       // [76][68]  = 5168
#define OFF_W   5168                    // 21504 floats, aliased:
#define OFF_XS  OFF_W                   //   [32][68] = 2176
#define OFF_BS  (OFF_W + 2176)          //   [32][84] = 2688
#define OFF_CS  OFF_W                   //   [76][132] = 10032
#define OFF_HT  (OFF_W + 21504)         // [256][68] = 17408  (GELU output, col-major)
#define OFF_ZS  (OFF_HT + 17408)        // [76][68]  = 5168
#define SMEM_FLOATS (OFF_ZS + 5168)     // 49248
#define SMEM_BYTES  (SMEM_FLOATS * 4)   // 196992 B

// Precomputed tables (device globals: no allocation allowed)
__device__ float g_B[IN_DIM * NFP];     // [n][k]  padded cols 76..79 = 0
__device__ float g_C[NF * IN_DIM];      // [k][n]
__device__ float g_W1T[2][NF * HID];    // [p][i][j] = w1[j][i]
__device__ float g_W2T[2][HID * NFP];   // [p][k][c] = w2[c][k], padded 0

__global__ void precompute_tables(const int* __restrict__ indices) {
    int t = blockIdx.x * blockDim.x + threadIdx.x;
    if (t >= IN_DIM * NFP) return;
    int n = t / NFP;
    int k = t - n * NFP;
    if (k >= NF) { g_B[n * NFP + k] = 0.f; return; }
    int f = indices[(k < KSEL) ? k : (k - KSEL)];
    long long m = ((long long)f * (long long)n) % IN_DIM;
    double th = (2.0 * 3.14159265358979323846 / (double)IN_DIM) * (double)m;
    double s, c;
    sincos(th, &s, &c);
    double bv = (k < KSEL) ? c : -s;
    double w = (f == 0 || 2 * f == IN_DIM) ? (1.0 / IN_DIM) : (2.0 / IN_DIM);
    g_B[n * NFP + k] = (float)bv;
    g_C[k * IN_DIM + n] = (float)(w * bv);
}

__global__ void precompute_wt(const float* __restrict__ mu_w1, const float* __restrict__ sg_w1,
                              const float* __restrict__ mu_w2, const float* __restrict__ sg_w2) {
    int t = blockIdx.x * blockDim.x + threadIdx.x;
    const int N1 = NF * HID;           // 19456 per p
    const int N2 = HID * NFP;          // 20480 per p
    if (t < 2 * N1) {
        int p = t / N1, r = t - p * N1;
        int i = r >> 8, j = r & 255;   // [i][j]
        const float* w1 = p ? sg_w1 : mu_w1;
        g_W1T[p][r] = w1[j * NF + i];
        return;
    }
    t -= 2 * N1;
    if (t < 2 * N2) {
        int p = t / N2, r = t - p * N2;
        int k = r / NFP, c = r - k * NFP;
        const float* w2 = p ? sg_w2 : mu_w2;
        g_W2T[p][r] = (c < NF) ? w2[c * HID + k] : 0.f;
    }
}

__global__ __launch_bounds__(THREADS, 1)
void fused_kernel(const float* __restrict__ x,
                  const float* __restrict__ eps,
                  const float* __restrict__ mu_b1, const float* __restrict__ mu_g,
                  const float* __restrict__ mu_beta, const float* __restrict__ mu_b2,
                  const float* __restrict__ sg_b1, const float* __restrict__ sg_g,
                  const float* __restrict__ sg_beta, const float* __restrict__ sg_b2,
                  float* __restrict__ out)
{
    extern __shared__ float sm[];
    float* XIN = sm + OFF_XIN;
    float* WB  = sm + OFF_W;
    float* XS  = sm + OFF_XS;
    float* BS  = sm + OFF_BS;
    float* CS  = sm + OFF_CS;
    float* HT  = sm + OFF_HT;
    float* ZS  = sm + OFF_ZS;

    const int tid  = threadIdx.x;
    const int tr   = tid >> 5;        // 0..15: rows tr*4 .. tr*4+3 (contiguous)
    const int tc16 = tid & 15;        // narrow-GEMM column owner
    const int s    = (tid >> 4) & 1;  // split-k half
    const int tc32 = tid & 31;        // wide-GEMM column owner
    const int r4   = tr * 4;
    const int row0 = blockIdx.x * ROWS;

    // ========== Phase 1: XIN[row][80 cols] = X[64][768] @ B (split-k by s) ==========
    float acc1[4][5];
    #pragma unroll
    for (int j = 0; j < 4; j++)
        #pragma unroll
        for (int l = 0; l < 5; l++) acc1[j][l] = 0.f;

    for (int kb = 0; kb < IN_DIM; kb += 32) {
        __syncthreads();
        {   // stage X chunk transposed: XS[k][row]
            int r = tid & 63, cc = (tid >> 6) * 4;
            float4 v = *reinterpret_cast<const float4*>(
                &x[(size_t)(row0 + r) * IN_DIM + kb + cc]);
            XS[(cc + 0) * SR + r] = v.x;
            XS[(cc + 1) * SR + r] = v.y;
            XS[(cc + 2) * SR + r] = v.z;
            XS[(cc + 3) * SR + r] = v.w;
        }
        for (int idx = tid; idx < 32 * 20; idx += THREADS) {
            int k = idx / 20, c4 = (idx - k * 20) * 4;
            *reinterpret_cast<float4*>(&BS[k * BSS + c4]) =
                *reinterpret_cast<const float4*>(&g_B[(kb + k) * NFP + c4]);
        }
        __syncthreads();
        const int k0 = s * 16;
        #pragma unroll
        for (int kt = 0; kt < 16; kt++) {
            int kk = k0 + kt;
            float4 av = *reinterpret_cast<const float4*>(&XS[kk * SR + r4]);
            float4 bv = *reinterpret_cast<const float4*>(&BS[kk * BSS + tc16 * 4]);
            float  b4 = BS[kk * BSS + 64 + tc16];
            float a[4] = {av.x, av.y, av.z, av.w};
            float b[5] = {bv.x, bv.y, bv.z, bv.w, b4};
            #pragma unroll
            for (int j = 0; j < 4; j++)
                #pragma unroll
                for (int l = 0; l < 5; l++)
                    acc1[j][l] = fmaf(a[j], b[l], acc1[j][l]);
        }
    }
    #pragma unroll
    for (int j = 0; j < 4; j++)
        #pragma unroll
        for (int l = 0; l < 5; l++)
            acc1[j][l] += __shfl_xor_sync(0xffffffffu, acc1[j][l], 16);
    if (s == 0) {
        #pragma unroll
        for (int l = 0; l < 5; l++) {
            int c = (l < 4) ? tc16 * 4 + l : 64 + tc16;
            if (c < NF) {
                float4 v = make_float4(acc1[0][l], acc1[1][l], acc1[2][l], acc1[3][l]);
                *reinterpret_cast<float4*>(&XIN[c * SR + r4]) = v;
            }
        }
    }

    // ========== Phase 2: two MLPs ==========
    float zmu[4][5];
    #pragma unroll 1
    for (int p = 0; p < 2; p++) {
        const float* b1 = p ? sg_b1 : mu_b1;
        const float* gp = p ? sg_g : mu_g;
        const float* bp = p ? sg_beta : mu_beta;
        const float* b2 = p ? sg_b2 : mu_b2;
        const float* w1t = g_W1T[p];
        const float* w2t = g_W2T[p];

        __syncthreads();   // XIN visible (p=0) / WB free
        for (int idx = tid; idx < NF * 64; idx += THREADS) {
            int i = idx >> 6, j4 = (idx & 63) * 4;
            *reinterpret_cast<float4*>(&WB[i * W1S + j4]) =
                *reinterpret_cast<const float4*>(&w1t[i * HID + j4]);
        }
        __syncthreads();

        // GEMM1: H[64][256] = XIN @ W1^T  (all 32 lanes = columns)
        float acc[4][8];
        #pragma unroll
        for (int j = 0; j < 4; j++)
            #pragma unroll
            for (int l = 0; l < 8; l++) acc[j][l] = 0.f;
        for (int i = 0; i < NF; i++) {
            float4 av  = *reinterpret_cast<const float4*>(&XIN[i * SR + r4]);
            float4 bv0 = *reinterpret_cast<const float4*>(&WB[i * W1S + tc32 * 4]);
            float4 bv1 = *reinterpret_cast<const float4*>(&WB[i * W1S + 128 + tc32 * 4]);
            float a[4] = {av.x, av.y, av.z, av.w};
            float b[8] = {bv0.x, bv0.y, bv0.z, bv0.w, bv1.x, bv1.y, bv1.z, bv1.w};
            #pragma unroll
            for (int j = 0; j < 4; j++)
                #pragma unroll
                for (int l = 0; l < 8; l++)
                    acc[j][l] = fmaf(a[j], b[l], acc[j][l]);
        }

        // LayerNorm + exact GELU fully in registers (row = 32-lane warp reduce)
        {
            float4 q0 = __ldg(reinterpret_cast<const float4*>(&b1[tc32 * 4]));
            float4 q1 = __ldg(reinterpret_cast<const float4*>(&b1[128 + tc32 * 4]));
            float4 g0 = __ldg(reinterpret_cast<const float4*>(&gp[tc32 * 4]));
            float4 g1 = __ldg(reinterpret_cast<const float4*>(&gp[128 + tc32 * 4]));
            float4 e0 = __ldg(reinterpret_cast<const float4*>(&bp[tc32 * 4]));
            float4 e1 = __ldg(reinterpret_cast<const float4*>(&bp[128 + tc32 * 4]));
            float bb[8] = {q0.x, q0.y, q0.z, q0.w, q1.x, q1.y, q1.z, q1.w};
            float gg[8] = {g0.x, g0.y, g0.z, g0.w, g1.x, g1.y, g1.z, g1.w};
            float bt[8] = {e0.x, e0.y, e0.z, e0.w, e1.x, e1.y, e1.z, e1.w};
            #pragma unroll
            for (int j = 0; j < 4; j++) {
                float sv = 0.f, sq = 0.f;
                #pragma unroll
                for (int m = 0; m < 8; m++) {
                    acc[j][m] += bb[m];
                    sv += acc[j][m];
                    sq = fmaf(acc[j][m], acc[j][m], sq);
                }
                #pragma unroll
                for (int o = 16; o > 0; o >>= 1) {
                    sv += __shfl_xor_sync(0xffffffffu, sv, o);
                    sq += __shfl_xor_sync(0xffffffffu, sq, o);
                }
                float mean = sv * (1.f / HID);
                float inv  = rsqrtf(sq * (1.f / HID) - mean * mean + 1e-5f);
                #pragma unroll
                for (int m = 0; m < 8; m++) {
                    float hn = (acc[j][m] - mean) * inv * gg[m] + bt[m];
                    acc[j][m] = 0.5f * hn * (1.f + erff(hn * 0.70710678118654752f));
                }
            }
        }
        #pragma unroll
        for (int m = 0; m < 8; m++) {
            int col = (m < 4) ? tc32 * 4 + m : 128 + tc32 * 4 + (m - 4);
            float4 v = make_float4(acc[0][m], acc[1][m], acc[2][m], acc[3][m]);
            *reinterpret_cast<float4*>(&HT[col * SR + r4]) = v;
        }
        __syncthreads();   // HT ready; GEMM1 done reading WB

        for (int idx = tid; idx < HID * 20; idx += THREADS) {
            int k = idx / 20, c4 = (idx - k * 20) * 4;
            *reinterpret_cast<float4*>(&WB[k * W2S + c4]) =
                *reinterpret_cast<const float4*>(&w2t[k * NFP + c4]);
        }
        __syncthreads();

        // GEMM2: Z[64][80] = gelu(H) @ W2^T (split-k by s)
        float acc2[4][5];
        #pragma unroll
        for (int j = 0; j < 4; j++)
            #pragma unroll
            for (int l = 0; l < 5; l++) acc2[j][l] = 0.f;
        const int kbase = s * 128;
        for (int kt = 0; kt < 128; kt++) {
            int k = kbase + kt;
            float4 av = *reinterpret_cast<const float4*>(&HT[k * SR + r4]);
            float4 bv = *reinterpret_cast<const float4*>(&WB[k * W2S + tc16 * 4]);
            float  b4 = WB[k * W2S + 64 + tc16];
            float a[4] = {av.x, av.y, av.z, av.w};
            float b[5] = {bv.x, bv.y, bv.z, bv.w, b4};
            #pragma unroll
            for (int j = 0; j < 4; j++)
                #pragma unroll
                for (int l = 0; l < 5; l++)
                    acc2[j][l] = fmaf(a[j], b[l], acc2[j][l]);
        }
        #pragma unroll
        for (int j = 0; j < 4; j++)
            #pragma unroll
            for (int l = 0; l < 5; l++)
                acc2[j][l] += __shfl_xor_sync(0xffffffffu, acc2[j][l], 16);

        float4 b2v = __ldg(reinterpret_cast<const float4*>(&b2[tc16 * 4]));
        float  b2s = (tc16 < 12) ? __ldg(&b2[64 + tc16]) : 0.f;
        float bb2[5] = {b2v.x, b2v.y, b2v.z, b2v.w, b2s};
        if (p == 0) {
            #pragma unroll
            for (int j = 0; j < 4; j++)
                #pragma unroll
                for (int l = 0; l < 5; l++)
                    zmu[j][l] = acc2[j][l] + bb2[l];
        } else if (s == 0) {
            float z[4][5];
            #pragma unroll
            for (int j = 0; j < 4; j++) {
                int row = row0 + r4 + j;
                float4 ev = __ldg(reinterpret_cast<const float4*>(&eps[(size_t)row * NF + tc16 * 4]));
                float ee[5] = {ev.x, ev.y, ev.z, ev.w,
                               (tc16 < 12) ? __ldg(&eps[(size_t)row * NF + 64 + tc16]) : 0.f};
                #pragma unroll
                for (int l = 0; l < 5; l++)
                    z[j][l] = fmaf(ee[l], acc2[j][l] + bb2[l], zmu[j][l]);
            }
            #pragma unroll
            for (int l = 0; l < 5; l++) {
                int c = (l < 4) ? tc16 * 4 + l : 64 + tc16;
                if (c < NF) {
                    float4 v = make_float4(z[0][l], z[1][l], z[2][l], z[3][l]);
                    *reinterpret_cast<float4*>(&ZS[c * SR + r4]) = v;
                }
            }
        }
    }

    // ========== Phase 3: out[64][768] = Z @ C (split-k by s) ==========
    for (int nc = 0; nc < IN_DIM; nc += 128) {
        __syncthreads();   // ZS visible / WB free
        for (int idx = tid; idx < NF * 32; idx += THREADS) {
            int k = idx >> 5, c4 = (idx & 31) * 4;
            *reinterpret_cast<float4*>(&CS[k * CSS + c4]) =
                *reinterpret_cast<const float4*>(&g_C[k * IN_DIM + nc + c4]);
        }
        __syncthreads();
        float acc3[4][8];
        #pragma unroll
        for (int j = 0; j < 4; j++)
            #pragma unroll
            for (int l = 0; l < 8; l++) acc3[j][l] = 0.f;
        const int kb3 = s * 38;
        for (int kt = 0; kt < 38; kt++) {
            int k = kb3 + kt;
            float4 av  = *reinterpret_cast<const float4*>(&ZS[k * SR + r4]);
            float4 bv0 = *reinterpret_cast<const float4*>(&CS[k * CSS + tc16 * 4]);
            float4 bv1 = *reinterpret_cast<const float4*>(&CS[k * CSS + 64 + tc16 * 4]);
            float a[4] = {av.x, av.y, av.z, av.w};
            float b[8] = {bv0.x, bv0.y, bv0.z, bv0.w, bv1.x, bv1.y, bv1.z, bv1.w};
            #pragma unroll
            for (int j = 0; j < 4; j++)
                #pragma unroll
                for (int l = 0; l < 8; l++)
                    acc3[j][l] = fmaf(a[j], b[l], acc3[j][l]);
        }
        #pragma unroll
        for (int j = 0; j < 4; j++)
            #pragma unroll
            for (int l = 0; l < 8; l++)
                acc3[j][l] += __shfl_xor_sync(0xffffffffu, acc3[j][l], 16);
        if (s == 0) {
            #pragma unroll
            for (int j = 0; j < 4; j++) {
                size_t base = (size_t)(row0 + r4 + j) * IN_DIM + nc;
                *reinterpret_cast<float4*>(&out[base + tc16 * 4]) =
                    make_float4(acc3[j][0], acc3[j][1], acc3[j][2], acc3[j][3]);
                *reinterpret_cast<float4*>(&out[base + 64 + tc16 * 4]) =
                    make_float4(acc3[j][4], acc3[j][5], acc3[j][6], acc3[j][7]);
            }
        }
    }
}

extern "C" void kernel_launch(void* const* d_in, const int* in_sizes, int n_in,
                              void* d_out, int out_size) {
    const float* x       = (const float*)d_in[0];
    const float* eps     = (const float*)d_in[1];
    const int*   indices = (const int*)  d_in[2];
    const float* mu_w1   = (const float*)d_in[3];
    const float* mu_b1   = (const float*)d_in[4];
    const float* mu_g    = (const float*)d_in[5];
    const float* mu_beta = (const float*)d_in[6];
    const float* mu_w2   = (const float*)d_in[7];
    const float* mu_b2   = (const float*)d_in[8];
    const float* sg_w1   = (const float*)d_in[9];
    const float* sg_b1   = (const float*)d_in[10];
    const float* sg_g    = (const float*)d_in[11];
    const float* sg_beta = (const float*)d_in[12];
    const float* sg_w2   = (const float*)d_in[13];
    const float* sg_b2   = (const float*)d_in[14];
    float* out = (float*)d_out;

    int n_rows = in_sizes[0] / IN_DIM;   // 32768

    cudaFuncSetAttribute(fused_kernel,
                         cudaFuncAttributeMaxDynamicSharedMemorySize, SMEM_BYTES);

    precompute_tables<<<(IN_DIM * NFP + 255) / 256, 256>>>(indices);
    int wt_total = 2 * NF * HID + 2 * HID * NFP;
    precompute_wt<<<(wt_total + 255) / 256, 256>>>(mu_w1, sg_w1, mu_w2, sg_w2);

    fused_kernel<<<n_rows / ROWS, THREADS, SMEM_BYTES>>>(
        x, eps,
        mu_b1, mu_g, mu_beta, mu_b2,
        sg_b1, sg_g, sg_beta, sg_b2,
        out);
}

// round 8
// speedup vs baseline: 2.0537x; 1.1407x over previous
#include <cuda_runtime.h>
#include <math.h>

#define IN_DIM 768
#define KSEL   38
#define NF     76     // MLP_IN
#define NFP    80     // padded to multiple of 16
#define HID    256
#define ROWS   64
#define THREADS 512

// shared-memory strides (floats)
#define SR   68       // [.][row] buffers: 272B = 17*16 (float4-aligned, bank-skewed)
#define W1S  260      // W1^T rows (1040B = 65*16)
#define W2S  84       // W2^T rows (336B = 21*16)
#define CSS  132      // C tile rows (528B = 33*16)
#define BSS  84       // B tile rows

// smem layout (float offsets)
#define OFF_XIN 0                       // [76][68]  = 5168
#define OFF_W   5168                    // 21504 floats, aliased:
#define OFF_XS  OFF_W                   //   [32][68] = 2176
#define OFF_BS  (OFF_W + 2176)          //   [32][84] = 2688
#define OFF_CS  OFF_W                   //   [76][132] = 10032
#define OFF_HT  (OFF_W + 21504)         // [256][68] = 17408
#define OFF_ZS  (OFF_HT + 17408)        // [76][68]  = 5168
#define SMEM_FLOATS (OFF_ZS + 5168)     // 49248
#define SMEM_BYTES  (SMEM_FLOATS * 4)   // 196992 B

// ---- packed f32x2 helpers (Blackwell FFMA2 — only reachable via PTX) ----
typedef unsigned long long u64;

__device__ __forceinline__ void ffma2(u64& d, u64 a, u64 b) {
    asm("fma.rn.f32x2 %0, %1, %2, %0;" : "+l"(d) : "l"(a), "l"(b));
}
__device__ __forceinline__ u64 bcast2(float a) {
    u64 r;
    asm("mov.b64 %0, {%1, %1};" : "=l"(r) : "f"(a));
    return r;
}
__device__ __forceinline__ float2 unpack2(u64 v) {
    float2 r;
    asm("mov.b64 {%0, %1}, %2;" : "=f"(r.x), "=f"(r.y) : "l"(v));
    return r;
}

// Precomputed tables (device globals: no allocation allowed)
__device__ float g_B[IN_DIM * NFP];     // [n][k]  padded cols 76..79 = 0
__device__ float g_C[NF * IN_DIM];      // [k][n]
__device__ float g_W1T[2][NF * HID];    // [p][i][j] = w1[j][i]
__device__ float g_W2T[2][HID * NFP];   // [p][k][c] = w2[c][k], padded 0

__global__ void precompute_all(const int* __restrict__ indices,
                               const float* __restrict__ mu_w1, const float* __restrict__ sg_w1,
                               const float* __restrict__ mu_w2, const float* __restrict__ sg_w2) {
    int t = blockIdx.x * blockDim.x + threadIdx.x;
    if (t < IN_DIM * NFP) {
        int n = t / NFP;
        int k = t - n * NFP;
        if (k >= NF) { g_B[n * NFP + k] = 0.f; return; }
        int f = indices[(k < KSEL) ? k : (k - KSEL)];
        int m = (f * n) % IN_DIM;                 // f<384, n<768 → fits int
        float s, c;
        sincospif((float)m * (1.0f / 384.0f), &s, &c);   // 2*pi*m/768
        float bv = (k < KSEL) ? c : -s;
        float w = (f == 0 || 2 * f == IN_DIM) ? (1.0f / IN_DIM) : (2.0f / IN_DIM);
        g_B[n * NFP + k] = bv;
        g_C[k * IN_DIM + n] = w * bv;
        return;
    }
    t -= IN_DIM * NFP;
    const int N1 = NF * HID;           // 19456 per p
    const int N2 = HID * NFP;          // 20480 per p
    if (t < 2 * N1) {
        int p = t / N1, r = t - p * N1;
        int i = r >> 8, j = r & 255;
        const float* w1 = p ? sg_w1 : mu_w1;
        g_W1T[p][r] = w1[j * NF + i];
        return;
    }
    t -= 2 * N1;
    if (t < 2 * N2) {
        int p = t / N2, r = t - p * N2;
        int k = r / NFP, c = r - k * NFP;
        const float* w2 = p ? sg_w2 : mu_w2;
        g_W2T[p][r] = (c < NF) ? w2[c * HID + k] : 0.f;
    }
}

__global__ __launch_bounds__(THREADS, 1)
void fused_kernel(const float* __restrict__ x,
                  const float* __restrict__ eps,
                  const float* __restrict__ mu_b1, const float* __restrict__ mu_g,
                  const float* __restrict__ mu_beta, const float* __restrict__ mu_b2,
                  const float* __restrict__ sg_b1, const float* __restrict__ sg_g,
                  const float* __restrict__ sg_beta, const float* __restrict__ sg_b2,
                  float* __restrict__ out)
{
    extern __shared__ float sm[];
    float* XIN = sm + OFF_XIN;
    float* WB  = sm + OFF_W;
    float* XS  = sm + OFF_XS;
    float* BS  = sm + OFF_BS;
    float* CS  = sm + OFF_CS;
    float* HT  = sm + OFF_HT;
    float* ZS  = sm + OFF_ZS;

    const int tid  = threadIdx.x;
    const int tr   = tid >> 5;        // 0..15: rows tr*4 .. tr*4+3
    const int tc16 = tid & 15;        // narrow-GEMM column owner
    const int s    = (tid >> 4) & 1;  // split-k half
    const int tc32 = tid & 31;        // wide-GEMM column owner
    const int r4   = tr * 4;
    const int row0 = blockIdx.x * ROWS;

    // ========== Phase 1: XIN[64][80] = X[64][768] @ B (split-k by s) ==========
    u64 acc1p[4][2];
    float acc1s[4];
    #pragma unroll
    for (int j = 0; j < 4; j++) { acc1p[j][0] = 0; acc1p[j][1] = 0; acc1s[j] = 0.f; }

    for (int kb = 0; kb < IN_DIM; kb += 32) {
        __syncthreads();
        {   // stage X chunk transposed: XS[k][row]
            int r = tid & 63, cc = (tid >> 6) * 4;
            float4 v = *reinterpret_cast<const float4*>(
                &x[(size_t)(row0 + r) * IN_DIM + kb + cc]);
            XS[(cc + 0) * SR + r] = v.x;
            XS[(cc + 1) * SR + r] = v.y;
            XS[(cc + 2) * SR + r] = v.z;
            XS[(cc + 3) * SR + r] = v.w;
        }
        for (int idx = tid; idx < 32 * 20; idx += THREADS) {
            int k = idx / 20, c4 = (idx - k * 20) * 4;
            *reinterpret_cast<float4*>(&BS[k * BSS + c4]) =
                *reinterpret_cast<const float4*>(&g_B[(kb + k) * NFP + c4]);
        }
        __syncthreads();
        const int k0 = s * 16;
        #pragma unroll
        for (int kt = 0; kt < 16; kt++) {
            int kk = k0 + kt;
            float4 av = *reinterpret_cast<const float4*>(&XS[kk * SR + r4]);
            ulonglong2 bq = *reinterpret_cast<const ulonglong2*>(&BS[kk * BSS + tc16 * 4]);
            float b4 = BS[kk * BSS + 64 + tc16];
            float a[4] = {av.x, av.y, av.z, av.w};
            #pragma unroll
            for (int j = 0; j < 4; j++) {
                u64 a2 = bcast2(a[j]);
                ffma2(acc1p[j][0], a2, bq.x);
                ffma2(acc1p[j][1], a2, bq.y);
                acc1s[j] = fmaf(a[j], b4, acc1s[j]);
            }
        }
    }
    {
        float acc1[4][5];
        #pragma unroll
        for (int j = 0; j < 4; j++) {
            float2 p0 = unpack2(acc1p[j][0]), p1 = unpack2(acc1p[j][1]);
            acc1[j][0] = p0.x; acc1[j][1] = p0.y;
            acc1[j][2] = p1.x; acc1[j][3] = p1.y;
            acc1[j][4] = acc1s[j];
        }
        #pragma unroll
        for (int j = 0; j < 4; j++)
            #pragma unroll
            for (int l = 0; l < 5; l++)
                acc1[j][l] += __shfl_xor_sync(0xffffffffu, acc1[j][l], 16);
        if (s == 0) {
            #pragma unroll
            for (int l = 0; l < 5; l++) {
                int c = (l < 4) ? tc16 * 4 + l : 64 + tc16;
                if (c < NF) {
                    float4 v = make_float4(acc1[0][l], acc1[1][l], acc1[2][l], acc1[3][l]);
                    *reinterpret_cast<float4*>(&XIN[c * SR + r4]) = v;
                }
            }
        }
    }

    // ========== Phase 2: two MLPs ==========
    float zmu[4][5];
    #pragma unroll 1
    for (int p = 0; p < 2; p++) {
        const float* b1 = p ? sg_b1 : mu_b1;
        const float* gp = p ? sg_g : mu_g;
        const float* bp = p ? sg_beta : mu_beta;
        const float* b2 = p ? sg_b2 : mu_b2;
        const float* w1t = g_W1T[p];
        const float* w2t = g_W2T[p];

        __syncthreads();   // XIN visible (p=0) / WB free
        for (int idx = tid; idx < NF * 64; idx += THREADS) {
            int i = idx >> 6, j4 = (idx & 63) * 4;
            *reinterpret_cast<float4*>(&WB[i * W1S + j4]) =
                *reinterpret_cast<const float4*>(&w1t[i * HID + j4]);
        }
        __syncthreads();

        // GEMM1: H[64][256] = XIN @ W1^T  (all 32 lanes = columns, FFMA2)
        u64 accp[4][4];
        #pragma unroll
        for (int j = 0; j < 4; j++)
            #pragma unroll
            for (int l = 0; l < 4; l++) accp[j][l] = 0;
        for (int i = 0; i < NF; i++) {
            float4 av  = *reinterpret_cast<const float4*>(&XIN[i * SR + r4]);
            ulonglong2 b0 = *reinterpret_cast<const ulonglong2*>(&WB[i * W1S + tc32 * 4]);
            ulonglong2 b1q = *reinterpret_cast<const ulonglong2*>(&WB[i * W1S + 128 + tc32 * 4]);
            float a[4] = {av.x, av.y, av.z, av.w};
            #pragma unroll
            for (int j = 0; j < 4; j++) {
                u64 a2 = bcast2(a[j]);
                ffma2(accp[j][0], a2, b0.x);
                ffma2(accp[j][1], a2, b0.y);
                ffma2(accp[j][2], a2, b1q.x);
                ffma2(accp[j][3], a2, b1q.y);
            }
        }
        float acc[4][8];
        #pragma unroll
        for (int j = 0; j < 4; j++)
            #pragma unroll
            for (int l = 0; l < 4; l++) {
                float2 v = unpack2(accp[j][l]);
                acc[j][2 * l] = v.x; acc[j][2 * l + 1] = v.y;
            }

        // LayerNorm + exact GELU fully in registers
        {
            float4 q0 = __ldg(reinterpret_cast<const float4*>(&b1[tc32 * 4]));
            float4 q1 = __ldg(reinterpret_cast<const float4*>(&b1[128 + tc32 * 4]));
            float4 g0 = __ldg(reinterpret_cast<const float4*>(&gp[tc32 * 4]));
            float4 g1 = __ldg(reinterpret_cast<const float4*>(&gp[128 + tc32 * 4]));
            float4 e0 = __ldg(reinterpret_cast<const float4*>(&bp[tc32 * 4]));
            float4 e1 = __ldg(reinterpret_cast<const float4*>(&bp[128 + tc32 * 4]));
            float bb[8] = {q0.x, q0.y, q0.z, q0.w, q1.x, q1.y, q1.z, q1.w};
            float gg[8] = {g0.x, g0.y, g0.z, g0.w, g1.x, g1.y, g1.z, g1.w};
            float bt[8] = {e0.x, e0.y, e0.z, e0.w, e1.x, e1.y, e1.z, e1.w};
            #pragma unroll
            for (int j = 0; j < 4; j++) {
                float sv = 0.f, sq = 0.f;
                #pragma unroll
                for (int m = 0; m < 8; m++) {
                    acc[j][m] += bb[m];
                    sv += acc[j][m];
                    sq = fmaf(acc[j][m], acc[j][m], sq);
                }
                #pragma unroll
                for (int o = 16; o > 0; o >>= 1) {
                    sv += __shfl_xor_sync(0xffffffffu, sv, o);
                    sq += __shfl_xor_sync(0xffffffffu, sq, o);
                }
                float mean = sv * (1.f / HID);
                float inv  = rsqrtf(sq * (1.f / HID) - mean * mean + 1e-5f);
                #pragma unroll
                for (int m = 0; m < 8; m++) {
                    float hn = (acc[j][m] - mean) * inv * gg[m] + bt[m];
                    acc[j][m] = 0.5f * hn * (1.f + erff(hn * 0.70710678118654752f));
                }
            }
        }
        #pragma unroll
        for (int m = 0; m < 8; m++) {
            int col = (m < 4) ? tc32 * 4 + m : 128 + tc32 * 4 + (m - 4);
            float4 v = make_float4(acc[0][m], acc[1][m], acc[2][m], acc[3][m]);
            *reinterpret_cast<float4*>(&HT[col * SR + r4]) = v;
        }
        __syncthreads();   // HT ready; GEMM1 done reading WB

        for (int idx = tid; idx < HID * 20; idx += THREADS) {
            int k = idx / 20, c4 = (idx - k * 20) * 4;
            *reinterpret_cast<float4*>(&WB[k * W2S + c4]) =
                *reinterpret_cast<const float4*>(&w2t[k * NFP + c4]);
        }
        __syncthreads();

        // GEMM2: Z[64][80] = gelu(H) @ W2^T (split-k by s, FFMA2)
        u64 acc2p[4][2];
        float acc2s[4];
        #pragma unroll
        for (int j = 0; j < 4; j++) { acc2p[j][0] = 0; acc2p[j][1] = 0; acc2s[j] = 0.f; }
        const int kbase = s * 128;
        for (int kt = 0; kt < 128; kt++) {
            int k = kbase + kt;
            float4 av = *reinterpret_cast<const float4*>(&HT[k * SR + r4]);
            ulonglong2 bq = *reinterpret_cast<const ulonglong2*>(&WB[k * W2S + tc16 * 4]);
            float b4 = WB[k * W2S + 64 + tc16];
            float a[4] = {av.x, av.y, av.z, av.w};
            #pragma unroll
            for (int j = 0; j < 4; j++) {
                u64 a2 = bcast2(a[j]);
                ffma2(acc2p[j][0], a2, bq.x);
                ffma2(acc2p[j][1], a2, bq.y);
                acc2s[j] = fmaf(a[j], b4, acc2s[j]);
            }
        }
        float acc2[4][5];
        #pragma unroll
        for (int j = 0; j < 4; j++) {
            float2 p0 = unpack2(acc2p[j][0]), p1 = unpack2(acc2p[j][1]);
            acc2[j][0] = p0.x; acc2[j][1] = p0.y;
            acc2[j][2] = p1.x; acc2[j][3] = p1.y;
            acc2[j][4] = acc2s[j];
        }
        #pragma unroll
        for (int j = 0; j < 4; j++)
            #pragma unroll
            for (int l = 0; l < 5; l++)
                acc2[j][l] += __shfl_xor_sync(0xffffffffu, acc2[j][l], 16);

        float4 b2v = __ldg(reinterpret_cast<const float4*>(&b2[tc16 * 4]));
        float  b2s = (tc16 < 12) ? __ldg(&b2[64 + tc16]) : 0.f;
        float bb2[5] = {b2v.x, b2v.y, b2v.z, b2v.w, b2s};
        if (p == 0) {
            #pragma unroll
            for (int j = 0; j < 4; j++)
                #pragma unroll
                for (int l = 0; l < 5; l++)
                    zmu[j][l] = acc2[j][l] + bb2[l];
        } else if (s == 0) {
            float z[4][5];
            #pragma unroll
            for (int j = 0; j < 4; j++) {
                int row = row0 + r4 + j;
                float4 ev = __ldg(reinterpret_cast<const float4*>(&eps[(size_t)row * NF + tc16 * 4]));
                float ee[5] = {ev.x, ev.y, ev.z, ev.w,
                               (tc16 < 12) ? __ldg(&eps[(size_t)row * NF + 64 + tc16]) : 0.f};
                #pragma unroll
                for (int l = 0; l < 5; l++)
                    z[j][l] = fmaf(ee[l], acc2[j][l] + bb2[l], zmu[j][l]);
            }
            #pragma unroll
            for (int l = 0; l < 5; l++) {
                int c = (l < 4) ? tc16 * 4 + l : 64 + tc16;
                if (c < NF) {
                    float4 v = make_float4(z[0][l], z[1][l], z[2][l], z[3][l]);
                    *reinterpret_cast<float4*>(&ZS[c * SR + r4]) = v;
                }
            }
        }
    }

    // ========== Phase 3: out[64][768] = Z @ C (split-k by s, FFMA2) ==========
    for (int nc = 0; nc < IN_DIM; nc += 128) {
        __syncthreads();   // ZS visible / WB free
        for (int idx = tid; idx < NF * 32; idx += THREADS) {
            int k = idx >> 5, c4 = (idx & 31) * 4;
            *reinterpret_cast<float4*>(&CS[k * CSS + c4]) =
                *reinterpret_cast<const float4*>(&g_C[k * IN_DIM + nc + c4]);
        }
        __syncthreads();
        u64 acc3p[4][4];
        #pragma unroll
        for (int j = 0; j < 4; j++)
            #pragma unroll
            for (int l = 0; l < 4; l++) acc3p[j][l] = 0;
        const int kb3 = s * 38;
        for (int kt = 0; kt < 38; kt++) {
            int k = kb3 + kt;
            float4 av  = *reinterpret_cast<const float4*>(&ZS[k * SR + r4]);
            ulonglong2 b0 = *reinterpret_cast<const ulonglong2*>(&CS[k * CSS + tc16 * 4]);
            ulonglong2 b1q = *reinterpret_cast<const ulonglong2*>(&CS[k * CSS + 64 + tc16 * 4]);
            float a[4] = {av.x, av.y, av.z, av.w};
            #pragma unroll
            for (int j = 0; j < 4; j++) {
                u64 a2 = bcast2(a[j]);
                ffma2(acc3p[j][0], a2, b0.x);
                ffma2(acc3p[j][1], a2, b0.y);
                ffma2(acc3p[j][2], a2, b1q.x);
                ffma2(acc3p[j][3], a2, b1q.y);
            }
        }
        float acc3[4][8];
        #pragma unroll
        for (int j = 0; j < 4; j++)
            #pragma unroll
            for (int l = 0; l < 4; l++) {
                float2 v = unpack2(acc3p[j][l]);
                acc3[j][2 * l] = v.x; acc3[j][2 * l + 1] = v.y;
            }
        #pragma unroll
        for (int j = 0; j < 4; j++)
            #pragma unroll
            for (int l = 0; l < 8; l++)
                acc3[j][l] += __shfl_xor_sync(0xffffffffu, acc3[j][l], 16);
        if (s == 0) {
            #pragma unroll
            for (int j = 0; j < 4; j++) {
                size_t base = (size_t)(row0 + r4 + j) * IN_DIM + nc;
                *reinterpret_cast<float4*>(&out[base + tc16 * 4]) =
                    make_float4(acc3[j][0], acc3[j][1], acc3[j][2], acc3[j][3]);
                *reinterpret_cast<float4*>(&out[base + 64 + tc16 * 4]) =
                    make_float4(acc3[j][4], acc3[j][5], acc3[j][6], acc3[j][7]);
            }
        }
    }
}

extern "C" void kernel_launch(void* const* d_in, const int* in_sizes, int n_in,
                              void* d_out, int out_size) {
    const float* x       = (const float*)d_in[0];
    const float* eps     = (const float*)d_in[1];
    const int*   indices = (const int*)  d_in[2];
    const float* mu_w1   = (const float*)d_in[3];
    const float* mu_b1   = (const float*)d_in[4];
    const float* mu_g    = (const float*)d_in[5];
    const float* mu_beta = (const float*)d_in[6];
    const float* mu_w2   = (const float*)d_in[7];
    const float* mu_b2   = (const float*)d_in[8];
    const float* sg_w1   = (const float*)d_in[9];
    const float* sg_b1   = (const float*)d_in[10];
    const float* sg_g    = (const float*)d_in[11];
    const float* sg_beta = (const float*)d_in[12];
    const float* sg_w2   = (const float*)d_in[13];
    const float* sg_b2   = (const float*)d_in[14];
    float* out = (float*)d_out;

    int n_rows = in_sizes[0] / IN_DIM;   // 32768

    cudaFuncSetAttribute(fused_kernel,
                         cudaFuncAttributeMaxDynamicSharedMemorySize, SMEM_BYTES);

    int pre_total = IN_DIM * NFP + 2 * NF * HID + 2 * HID * NFP;
    precompute_all<<<(pre_total + 255) / 256, 256>>>(indices, mu_w1, sg_w1, mu_w2, sg_w2);

    fused_kernel<<<n_rows / ROWS, THREADS, SMEM_BYTES>>>(
        x, eps,
        mu_b1, mu_g, mu_beta, mu_b2,
        sg_b1, sg_g, sg_beta, sg_b2,
        out);
}

// round 9
// speedup vs baseline: 2.1031x; 1.0240x over previous
#include <cuda_runtime.h>
#include <math.h>

#define IN_DIM 768
#define KSEL   38
#define NF     76     // MLP_IN
#define NFP    80     // padded to multiple of 16
#define HID    256
#define ROWS   64
#define THREADS 512

// shared-memory strides (floats)
#define SR   68       // [.][row] buffers: 272B = 17*16
#define W1S  260      // W1^T rows
#define W2S  84       // W2^T rows
#define CSS  132      // C tile rows
#define BSS  84       // B tile rows

// smem layout (float offsets)
#define OFF_XIN 0                       // [76][68]  = 5168
#define OFF_W   5168                    // 21504 floats, aliased:
#define OFF_XS  OFF_W                   //   [64][68] = 4352
#define OFF_BS  (OFF_W + 4352)          //   [64][84] = 5376
#define OFF_CS  OFF_W                   //   [76][132] = 10032
#define OFF_HT  (OFF_W + 21504)         // [256][68] = 17408
#define OFF_ZS  (OFF_HT + 17408)        // [76][68]  = 5168
#define OFF_LNS (OFF_ZS + 5168)         // [64][4] LN partial stats = 256
#define SMEM_FLOATS (OFF_LNS + 256)     // 49504
#define SMEM_BYTES  (SMEM_FLOATS * 4)   // 198016 B

// ---- packed f32x2 helpers (Blackwell FFMA2 — only reachable via PTX) ----
typedef unsigned long long u64;

__device__ __forceinline__ void ffma2(u64& d, u64 a, u64 b) {
    asm("fma.rn.f32x2 %0, %1, %2, %0;" : "+l"(d) : "l"(a), "l"(b));
}
__device__ __forceinline__ u64 bcast2(float a) {
    u64 r;
    asm("mov.b64 %0, {%1, %1};" : "=l"(r) : "f"(a));
    return r;
}
__device__ __forceinline__ float2 unpack2(u64 v) {
    float2 r;
    asm("mov.b64 {%0, %1}, %2;" : "=f"(r.x), "=f"(r.y) : "l"(v));
    return r;
}

// Precomputed tables (device globals: no allocation allowed)
__device__ float g_B[IN_DIM * NFP];     // [n][k]  padded cols 76..79 = 0
__device__ float g_C[NF * IN_DIM];      // [k][n]
__device__ float g_W1T[2][NF * HID];    // [p][i][j] = w1[j][i]
__device__ float g_W2T[2][HID * NFP];   // [p][k][c] = w2[c][k], padded 0

__global__ void precompute_all(const int* __restrict__ indices,
                               const float* __restrict__ mu_w1, const float* __restrict__ sg_w1,
                               const float* __restrict__ mu_w2, const float* __restrict__ sg_w2) {
    int t = blockIdx.x * blockDim.x + threadIdx.x;
    if (t < IN_DIM * NFP) {
        int n = t / NFP;
        int k = t - n * NFP;
        if (k >= NF) { g_B[n * NFP + k] = 0.f; return; }
        int f = indices[(k < KSEL) ? k : (k - KSEL)];
        int m = (f * n) % IN_DIM;
        float s, c;
        sincospif((float)m * (1.0f / 384.0f), &s, &c);   // 2*pi*m/768
        float bv = (k < KSEL) ? c : -s;
        float w = (f == 0 || 2 * f == IN_DIM) ? (1.0f / IN_DIM) : (2.0f / IN_DIM);
        g_B[n * NFP + k] = bv;
        g_C[k * IN_DIM + n] = w * bv;
        return;
    }
    t -= IN_DIM * NFP;
    const int N1 = NF * HID;
    const int N2 = HID * NFP;
    if (t < 2 * N1) {
        int p = t / N1, r = t - p * N1;
        int i = r >> 8, j = r & 255;
        const float* w1 = p ? sg_w1 : mu_w1;
        g_W1T[p][r] = w1[j * NF + i];
        return;
    }
    t -= 2 * N1;
    if (t < 2 * N2) {
        int p = t / N2, r = t - p * N2;
        int k = r / NFP, c = r - k * NFP;
        const float* w2 = p ? sg_w2 : mu_w2;
        g_W2T[p][r] = (c < NF) ? w2[c * HID + k] : 0.f;
    }
}

__global__ __launch_bounds__(THREADS, 1)
void fused_kernel(const float* __restrict__ x,
                  const float* __restrict__ eps,
                  const float* __restrict__ mu_b1, const float* __restrict__ mu_g,
                  const float* __restrict__ mu_beta, const float* __restrict__ mu_b2,
                  const float* __restrict__ sg_b1, const float* __restrict__ sg_g,
                  const float* __restrict__ sg_beta, const float* __restrict__ sg_b2,
                  float* __restrict__ out)
{
    extern __shared__ float sm[];
    float* XIN = sm + OFF_XIN;
    float* WB  = sm + OFF_W;
    float* XS  = sm + OFF_XS;
    float* BS  = sm + OFF_BS;
    float* CS  = sm + OFF_CS;
    float* HT  = sm + OFF_HT;
    float* ZS  = sm + OFF_ZS;
    float* LNS = sm + OFF_LNS;

    const int tid  = threadIdx.x;
    const int w    = tid >> 5;
    const int lane = tid & 31;
    const int tr   = w;               // narrow-GEMM: rows tr*4..+3
    const int tc16 = lane & 15;
    const int s    = lane >> 4;       // split-k half
    const int r4   = tr * 4;
    // wide-GEMM (8-row) mapping
    const int rg   = w & 7;           // 8-row group
    const int ch   = w >> 3;          // column half
    const int r8   = rg * 8;
    const int row0 = blockIdx.x * ROWS;

    // ========== Phase 1: XIN[64][80] = X[64][768] @ B (split-k by s) ==========
    u64 acc1p[4][2];
    float acc1s[4];
    #pragma unroll
    for (int j = 0; j < 4; j++) { acc1p[j][0] = 0; acc1p[j][1] = 0; acc1s[j] = 0.f; }

    for (int kb = 0; kb < IN_DIM; kb += 64) {
        __syncthreads();
        {   // stage 64 rows x 64 k of x, transposed: XS[k][row]
            int r = tid & 63, cc = (tid >> 6) * 8;
            const float* xp = &x[(size_t)(row0 + r) * IN_DIM + kb + cc];
            float4 v0 = *reinterpret_cast<const float4*>(xp);
            float4 v1 = *reinterpret_cast<const float4*>(xp + 4);
            XS[(cc + 0) * SR + r] = v0.x;
            XS[(cc + 1) * SR + r] = v0.y;
            XS[(cc + 2) * SR + r] = v0.z;
            XS[(cc + 3) * SR + r] = v0.w;
            XS[(cc + 4) * SR + r] = v1.x;
            XS[(cc + 5) * SR + r] = v1.y;
            XS[(cc + 6) * SR + r] = v1.z;
            XS[(cc + 7) * SR + r] = v1.w;
        }
        for (int idx = tid; idx < 64 * 20; idx += THREADS) {
            int k = idx / 20, c4 = (idx - k * 20) * 4;
            *reinterpret_cast<float4*>(&BS[k * BSS + c4]) =
                *reinterpret_cast<const float4*>(&g_B[(kb + k) * NFP + c4]);
        }
        __syncthreads();
        const int k0 = s * 32;
        #pragma unroll 4
        for (int kt = 0; kt < 32; kt++) {
            int kk = k0 + kt;
            float4 av = *reinterpret_cast<const float4*>(&XS[kk * SR + r4]);
            ulonglong2 bq = *reinterpret_cast<const ulonglong2*>(&BS[kk * BSS + tc16 * 4]);
            float b4 = BS[kk * BSS + 64 + tc16];
            float a[4] = {av.x, av.y, av.z, av.w};
            #pragma unroll
            for (int j = 0; j < 4; j++) {
                u64 a2 = bcast2(a[j]);
                ffma2(acc1p[j][0], a2, bq.x);
                ffma2(acc1p[j][1], a2, bq.y);
                acc1s[j] = fmaf(a[j], b4, acc1s[j]);
            }
        }
    }
    {
        float acc1[4][5];
        #pragma unroll
        for (int j = 0; j < 4; j++) {
            float2 p0 = unpack2(acc1p[j][0]), p1 = unpack2(acc1p[j][1]);
            acc1[j][0] = p0.x; acc1[j][1] = p0.y;
            acc1[j][2] = p1.x; acc1[j][3] = p1.y;
            acc1[j][4] = acc1s[j];
        }
        #pragma unroll
        for (int j = 0; j < 4; j++)
            #pragma unroll
            for (int l = 0; l < 5; l++)
                acc1[j][l] += __shfl_xor_sync(0xffffffffu, acc1[j][l], 16);
        if (s == 0) {
            #pragma unroll
            for (int l = 0; l < 5; l++) {
                int c = (l < 4) ? tc16 * 4 + l : 64 + tc16;
                if (c < NF) {
                    float4 v = make_float4(acc1[0][l], acc1[1][l], acc1[2][l], acc1[3][l]);
                    *reinterpret_cast<float4*>(&XIN[c * SR + r4]) = v;
                }
            }
        }
    }

    // ========== Phase 2: two MLPs ==========
    float zmu[4][5];
    #pragma unroll 1
    for (int p = 0; p < 2; p++) {
        const float* b1 = p ? sg_b1 : mu_b1;
        const float* gp = p ? sg_g : mu_g;
        const float* bp = p ? sg_beta : mu_beta;
        const float* b2 = p ? sg_b2 : mu_b2;
        const float* w1t = g_W1T[p];
        const float* w2t = g_W2T[p];

        __syncthreads();   // XIN visible (p=0) / WB free
        for (int idx = tid; idx < NF * 64; idx += THREADS) {
            int i = idx >> 6, j4 = (idx & 63) * 4;
            *reinterpret_cast<float4*>(&WB[i * W1S + j4]) =
                *reinterpret_cast<const float4*>(&w1t[i * HID + j4]);
        }
        __syncthreads();

        // GEMM1: H[64][256] = XIN @ W1^T — 8-row warp tiles, split-k by s.
        // Warp owns rows r8..r8+7 (A broadcast); lane owns 8 cols c0..c0+7.
        const int c0 = ch * 128 + tc16 * 8;
        u64 accp[8][4];
        #pragma unroll
        for (int r = 0; r < 8; r++)
            #pragma unroll
            for (int q = 0; q < 4; q++) accp[r][q] = 0;
        const int i0 = s * 38;
        #pragma unroll 2
        for (int it = 0; it < 38; it++) {
            int i = i0 + it;
            float4 a0 = *reinterpret_cast<const float4*>(&XIN[i * SR + r8]);
            float4 a1 = *reinterpret_cast<const float4*>(&XIN[i * SR + r8 + 4]);
            const float* wrow = &WB[i * W1S + c0];
            ulonglong2 bq0 = *reinterpret_cast<const ulonglong2*>(wrow);
            ulonglong2 bq1 = *reinterpret_cast<const ulonglong2*>(wrow + 4);
            float a[8] = {a0.x, a0.y, a0.z, a0.w, a1.x, a1.y, a1.z, a1.w};
            #pragma unroll
            for (int r = 0; r < 8; r++) {
                u64 a2 = bcast2(a[r]);
                ffma2(accp[r][0], a2, bq0.x);
                ffma2(accp[r][1], a2, bq0.y);
                ffma2(accp[r][2], a2, bq1.x);
                ffma2(accp[r][3], a2, bq1.y);
            }
        }
        float acc[8][8];
        #pragma unroll
        for (int r = 0; r < 8; r++)
            #pragma unroll
            for (int q = 0; q < 4; q++) {
                float2 v = unpack2(accp[r][q]);
                acc[r][2 * q] = v.x; acc[r][2 * q + 1] = v.y;
            }
        #pragma unroll
        for (int r = 0; r < 8; r++)
            #pragma unroll
            for (int c = 0; c < 8; c++)
                acc[r][c] += __shfl_xor_sync(0xffffffffu, acc[r][c], 16);

        // bias + per-warp partial LN stats over this col-half
        {
            float4 q0 = __ldg(reinterpret_cast<const float4*>(&b1[c0]));
            float4 q1 = __ldg(reinterpret_cast<const float4*>(&b1[c0 + 4]));
            float bb[8] = {q0.x, q0.y, q0.z, q0.w, q1.x, q1.y, q1.z, q1.w};
            float sv[8], sq[8];
            #pragma unroll
            for (int r = 0; r < 8; r++) {
                sv[r] = 0.f; sq[r] = 0.f;
                #pragma unroll
                for (int c = 0; c < 8; c++) {
                    acc[r][c] += bb[c];
                    sv[r] += acc[r][c];
                    sq[r] = fmaf(acc[r][c], acc[r][c], sq[r]);
                }
            }
            #pragma unroll
            for (int o = 1; o <= 8; o <<= 1) {
                #pragma unroll
                for (int r = 0; r < 8; r++) {
                    sv[r] += __shfl_xor_sync(0xffffffffu, sv[r], o);
                    sq[r] += __shfl_xor_sync(0xffffffffu, sq[r], o);
                }
            }
            if (lane == 0) {
                #pragma unroll
                for (int r = 0; r < 8; r++)
                    *reinterpret_cast<float2*>(&LNS[(r8 + r) * 4 + ch * 2]) =
                        make_float2(sv[r], sq[r]);
            }
        }
        __syncthreads();
        {
            float4 g0 = __ldg(reinterpret_cast<const float4*>(&gp[c0]));
            float4 g1 = __ldg(reinterpret_cast<const float4*>(&gp[c0 + 4]));
            float4 e0 = __ldg(reinterpret_cast<const float4*>(&bp[c0]));
            float4 e1 = __ldg(reinterpret_cast<const float4*>(&bp[c0 + 4]));
            float gg[8] = {g0.x, g0.y, g0.z, g0.w, g1.x, g1.y, g1.z, g1.w};
            float bt[8] = {e0.x, e0.y, e0.z, e0.w, e1.x, e1.y, e1.z, e1.w};
            #pragma unroll
            for (int r = 0; r < 8; r++) {
                float4 st = *reinterpret_cast<const float4*>(&LNS[(r8 + r) * 4]);
                float mean = (st.x + st.z) * (1.f / HID);
                float inv  = rsqrtf((st.y + st.w) * (1.f / HID) - mean * mean + 1e-5f);
                #pragma unroll
                for (int c = 0; c < 8; c++) {
                    float hn = (acc[r][c] - mean) * inv * gg[c] + bt[c];
                    acc[r][c] = 0.5f * hn * (1.f + erff(hn * 0.70710678118654752f));
                }
            }
        }
        if (s == 0) {
            #pragma unroll
            for (int c = 0; c < 8; c++) {
                *reinterpret_cast<float4*>(&HT[(c0 + c) * SR + r8]) =
                    make_float4(acc[0][c], acc[1][c], acc[2][c], acc[3][c]);
                *reinterpret_cast<float4*>(&HT[(c0 + c) * SR + r8 + 4]) =
                    make_float4(acc[4][c], acc[5][c], acc[6][c], acc[7][c]);
            }
        }
        __syncthreads();   // HT ready; GEMM1 done reading WB

        for (int idx = tid; idx < HID * 20; idx += THREADS) {
            int k = idx / 20, c4 = (idx - k * 20) * 4;
            *reinterpret_cast<float4*>(&WB[k * W2S + c4]) =
                *reinterpret_cast<const float4*>(&w2t[k * NFP + c4]);
        }
        __syncthreads();

        // GEMM2: Z[64][80] = gelu(H) @ W2^T (split-k by s, FFMA2)
        u64 acc2p[4][2];
        float acc2s[4];
        #pragma unroll
        for (int j = 0; j < 4; j++) { acc2p[j][0] = 0; acc2p[j][1] = 0; acc2s[j] = 0.f; }
        const int kbase = s * 128;
        #pragma unroll 4
        for (int kt = 0; kt < 128; kt++) {
            int k = kbase + kt;
            float4 av = *reinterpret_cast<const float4*>(&HT[k * SR + r4]);
            ulonglong2 bq = *reinterpret_cast<const ulonglong2*>(&WB[k * W2S + tc16 * 4]);
            float b4 = WB[k * W2S + 64 + tc16];
            float a[4] = {av.x, av.y, av.z, av.w};
            #pragma unroll
            for (int j = 0; j < 4; j++) {
                u64 a2 = bcast2(a[j]);
                ffma2(acc2p[j][0], a2, bq.x);
                ffma2(acc2p[j][1], a2, bq.y);
                acc2s[j] = fmaf(a[j], b4, acc2s[j]);
            }
        }
        float acc2[4][5];
        #pragma unroll
        for (int j = 0; j < 4; j++) {
            float2 p0 = unpack2(acc2p[j][0]), p1 = unpack2(acc2p[j][1]);
            acc2[j][0] = p0.x; acc2[j][1] = p0.y;
            acc2[j][2] = p1.x; acc2[j][3] = p1.y;
            acc2[j][4] = acc2s[j];
        }
        #pragma unroll
        for (int j = 0; j < 4; j++)
            #pragma unroll
            for (int l = 0; l < 5; l++)
                acc2[j][l] += __shfl_xor_sync(0xffffffffu, acc2[j][l], 16);

        float4 b2v = __ldg(reinterpret_cast<const float4*>(&b2[tc16 * 4]));
        float  b2s = (tc16 < 12) ? __ldg(&b2[64 + tc16]) : 0.f;
        float bb2[5] = {b2v.x, b2v.y, b2v.z, b2v.w, b2s};
        if (p == 0) {
            #pragma unroll
            for (int j = 0; j < 4; j++)
                #pragma unroll
                for (int l = 0; l < 5; l++)
                    zmu[j][l] = acc2[j][l] + bb2[l];
        } else if (s == 0) {
            float z[4][5];
            #pragma unroll
            for (int j = 0; j < 4; j++) {
                int row = row0 + r4 + j;
                float4 ev = __ldg(reinterpret_cast<const float4*>(&eps[(size_t)row * NF + tc16 * 4]));
                float ee[5] = {ev.x, ev.y, ev.z, ev.w,
                               (tc16 < 12) ? __ldg(&eps[(size_t)row * NF + 64 + tc16]) : 0.f};
                #pragma unroll
                for (int l = 0; l < 5; l++)
                    z[j][l] = fmaf(ee[l], acc2[j][l] + bb2[l], zmu[j][l]);
            }
            #pragma unroll
            for (int l = 0; l < 5; l++) {
                int c = (l < 4) ? tc16 * 4 + l : 64 + tc16;
                if (c < NF) {
                    float4 v = make_float4(z[0][l], z[1][l], z[2][l], z[3][l]);
                    *reinterpret_cast<float4*>(&ZS[c * SR + r4]) = v;
                }
            }
        }
    }

    // ========== Phase 3: out[64][768] = Z @ C — 8-row warp tiles, split-k ==========
    const int cc0 = ch * 64 + tc16 * 4;
    for (int nc = 0; nc < IN_DIM; nc += 128) {
        __syncthreads();   // ZS visible / WB free
        for (int idx = tid; idx < NF * 32; idx += THREADS) {
            int k = idx >> 5, c4 = (idx & 31) * 4;
            *reinterpret_cast<float4*>(&CS[k * CSS + c4]) =
                *reinterpret_cast<const float4*>(&g_C[k * IN_DIM + nc + c4]);
        }
        __syncthreads();
        u64 acc3p[8][2];
        #pragma unroll
        for (int r = 0; r < 8; r++) { acc3p[r][0] = 0; acc3p[r][1] = 0; }
        const int kb3 = s * 38;
        #pragma unroll 2
        for (int kt = 0; kt < 38; kt++) {
            int k = kb3 + kt;
            float4 a0 = *reinterpret_cast<const float4*>(&ZS[k * SR + r8]);
            float4 a1 = *reinterpret_cast<const float4*>(&ZS[k * SR + r8 + 4]);
            ulonglong2 bq = *reinterpret_cast<const ulonglong2*>(&CS[k * CSS + cc0]);
            float a[8] = {a0.x, a0.y, a0.z, a0.w, a1.x, a1.y, a1.z, a1.w};
            #pragma unroll
            for (int r = 0; r < 8; r++) {
                u64 a2 = bcast2(a[r]);
                ffma2(acc3p[r][0], a2, bq.x);
                ffma2(acc3p[r][1], a2, bq.y);
            }
        }
        float acc3[8][4];
        #pragma unroll
        for (int r = 0; r < 8; r++) {
            float2 v0 = unpack2(acc3p[r][0]), v1 = unpack2(acc3p[r][1]);
            acc3[r][0] = v0.x; acc3[r][1] = v0.y;
            acc3[r][2] = v1.x; acc3[r][3] = v1.y;
        }
        #pragma unroll
        for (int r = 0; r < 8; r++)
            #pragma unroll
            for (int l = 0; l < 4; l++)
                acc3[r][l] += __shfl_xor_sync(0xffffffffu, acc3[r][l], 16);
        if (s == 0) {
            #pragma unroll
            for (int r = 0; r < 8; r++) {
                *reinterpret_cast<float4*>(&out[(size_t)(row0 + r8 + r) * IN_DIM + nc + cc0]) =
                    make_float4(acc3[r][0], acc3[r][1], acc3[r][2], acc3[r][3]);
            }
        }
    }
}

extern "C" void kernel_launch(void* const* d_in, const int* in_sizes, int n_in,
                              void* d_out, int out_size) {
    const float* x       = (const float*)d_in[0];
    const float* eps     = (const float*)d_in[1];
    const int*   indices = (const int*)  d_in[2];
    const float* mu_w1   = (const float*)d_in[3];
    const float* mu_b1   = (const float*)d_in[4];
    const float* mu_g    = (const float*)d_in[5];
    const float* mu_beta = (const float*)d_in[6];
    const float* mu_w2   = (const float*)d_in[7];
    const float* mu_b2   = (const float*)d_in[8];
    const float* sg_w1   = (const float*)d_in[9];
    const float* sg_b1   = (const float*)d_in[10];
    const float* sg_g    = (const float*)d_in[11];
    const float* sg_beta = (const float*)d_in[12];
    const float* sg_w2   = (const float*)d_in[13];
    const float* sg_b2   = (const float*)d_in[14];
    float* out = (float*)d_out;

    int n_rows = in_sizes[0] / IN_DIM;   // 32768

    cudaFuncSetAttribute(fused_kernel,
                         cudaFuncAttributeMaxDynamicSharedMemorySize, SMEM_BYTES);

    int pre_total = IN_DIM * NFP + 2 * NF * HID + 2 * HID * NFP;
    precompute_all<<<(pre_total + 255) / 256, 256>>>(indices, mu_w1, sg_w1, mu_w2, sg_w2);

    fused_kernel<<<n_rows / ROWS, THREADS, SMEM_BYTES>>>(
        x, eps,
        mu_b1, mu_g, mu_beta, mu_b2,
        sg_b1, sg_g, sg_beta, sg_b2,
        out);
}

// round 10
// speedup vs baseline: 2.8591x; 1.3595x over previous
#include <cuda_runtime.h>
#include <math.h>

#define IN_DIM 768
#define KSEL   38
#define NF     76     // MLP_IN
#define NFP    80     // padded to multiple of 16
#define HID    256
#define ROWS   64
#define THREADS 512
#define KFOLD  384    // folded DFT K (f ≡ 1 mod 4 symmetry)

// shared-memory strides (floats)
#define SR   68
#define W1S  260
#define W2S  84
#define CSS  132
#define BSS  84

// smem layout (float offsets)
#define OFF_XIN 0                       // [76][68]  = 5168
#define OFF_W   5168                    // aliased scratch
#define OFF_XS  OFF_W                   //   [64][68] = 4352
#define OFF_BS  (OFF_W + 4352)          //   [64][84] = 5376
#define OFF_CS  OFF_W                   //   [76][132] = 10032
#define OFF_HT  (OFF_W + 21504)         // [256][68] = 17408
#define OFF_ZS  (OFF_HT + 17408)        // [76][68]  = 5168
#define OFF_LNS (OFF_ZS + 5168)         // [64][4]
#define SMEM_FLOATS (OFF_LNS + 256)
#define SMEM_BYTES  (SMEM_FLOATS * 4)   // 198016 B

typedef unsigned long long u64;

__device__ __forceinline__ void ffma2(u64& d, u64 a, u64 b) {
    asm("fma.rn.f32x2 %0, %1, %2, %0;" : "+l"(d) : "l"(a), "l"(b));
}
__device__ __forceinline__ u64 bcast2(float a) {
    u64 r;
    asm("mov.b64 %0, {%1, %1};" : "=l"(r) : "f"(a));
    return r;
}

// Precomputed tables
__device__ float g_B2[KFOLD * NFP];     // folded analysis: rows [d(192)|t(192)]
__device__ float g_C2[NF * KFOLD];      // folded synthesis: cols [Wre(192)|Wim(192)]
__device__ float g_W1T[2][NF * HID];
__device__ float g_W2T[2][HID * NFP];

__global__ void precompute_all(const int* __restrict__ indices,
                               const float* __restrict__ mu_w1, const float* __restrict__ sg_w1,
                               const float* __restrict__ mu_w2, const float* __restrict__ sg_w2) {
    int t = blockIdx.x * blockDim.x + threadIdx.x;
    if (t < KFOLD * NFP) {
        // analysis table: X_re[k] = sum_m d[m]*c - t[m]*s ; X_im = sum -d*s - t*c
        int kk = t / NFP, k = t - kk * NFP;
        if (k >= NF) { g_B2[t] = 0.f; return; }
        int f = indices[(k < KSEL) ? k : (k - KSEL)];
        int m = (kk < 192) ? kk : kk - 192;
        int mm = (f * m) % IN_DIM;
        float s, c;
        sincospif((float)mm * (1.0f / 384.0f), &s, &c);
        float v;
        if (kk < 192) v = (k < KSEL) ? c : -s;    // d-row
        else          v = (k < KSEL) ? -s : -c;   // t-row
        g_B2[t] = v;
        return;
    }
    t -= KFOLD * NFP;
    if (t < NF * KFOLD) {
        // synthesis: W[m] = sum_k w*(z_re + i z_im)*e^{+i theta}
        int k = t / KFOLD, cc = t - k * KFOLD;
        int f = indices[(k < KSEL) ? k : (k - KSEL)];
        int m = (cc < 192) ? cc : cc - 192;
        int mm = (f * m) % IN_DIM;
        float s, c;
        sincospif((float)mm * (1.0f / 384.0f), &s, &c);
        float w = (f == 0 || 2 * f == IN_DIM) ? (1.0f / IN_DIM) : (2.0f / IN_DIM);
        float v;
        if (cc < 192) v = (k < KSEL) ? (w * c) : (-w * s);   // Wre weights
        else          v = (k < KSEL) ? (w * s) : (w * c);    // Wim weights
        g_C2[t] = v;
        return;
    }
    t -= NF * KFOLD;
    const int N1 = NF * HID;
    const int N2 = HID * NFP;
    if (t < 2 * N1) {
        int p = t / N1, r = t - p * N1;
        int i = r >> 8, j = r & 255;
        const float* w1 = p ? sg_w1 : mu_w1;
        g_W1T[p][r] = w1[j * NF + i];
        return;
    }
    t -= 2 * N1;
    if (t < 2 * N2) {
        int p = t / N2, r = t - p * N2;
        int k = r / NFP, c = r - k * NFP;
        const float* w2 = p ? sg_w2 : mu_w2;
        g_W2T[p][r] = (c < NF) ? w2[c * HID + k] : 0.f;
    }
}

__global__ __launch_bounds__(THREADS, 1)
void fused_kernel(const float* __restrict__ x,
                  const float* __restrict__ eps,
                  const float* __restrict__ mu_b1, const float* __restrict__ mu_g,
                  const float* __restrict__ mu_beta, const float* __restrict__ mu_b2,
                  const float* __restrict__ sg_b1, const float* __restrict__ sg_g,
                  const float* __restrict__ sg_beta, const float* __restrict__ sg_b2,
                  float* __restrict__ out)
{
    extern __shared__ float sm[];
    float* XIN = sm + OFF_XIN;
    float* WB  = sm + OFF_W;
    float* XS  = sm + OFF_XS;
    float* BS  = sm + OFF_BS;
    float* CS  = sm + OFF_CS;
    float* HT  = sm + OFF_HT;
    float* ZS  = sm + OFF_ZS;
    float* LNS = sm + OFF_LNS;

    const int tid  = threadIdx.x;
    const int w    = tid >> 5;
    const int lane = tid & 31;
    const int tr   = w;
    const int tc16 = lane & 15;
    const int s    = lane >> 4;
    const int r4   = tr * 4;
    const int rg   = w & 7;
    const int ch   = w >> 3;
    const int r8   = rg * 8;
    const int row0 = blockIdx.x * ROWS;

    // ===== Phase 1: XIN[64][80] = [d|t][64][384] @ B2 (folded DFT, split-k) =====
    u64 acc1p[4][2];
    float acc1s[4];
    #pragma unroll
    for (int j = 0; j < 4; j++) { acc1p[j][0] = 0; acc1p[j][1] = 0; acc1s[j] = 0.f; }

    for (int kb = 0; kb < KFOLD; kb += 64) {
        __syncthreads();
        {   // stage folded differences: XS[k][row] = x[row][kb+c] - x[row][kb+384+c]
            int r = tid & 63, cc = (tid >> 6) * 8;
            const float* xp = &x[(size_t)(row0 + r) * IN_DIM + kb + cc];
            float4 v0 = *reinterpret_cast<const float4*>(xp);
            float4 v1 = *reinterpret_cast<const float4*>(xp + 4);
            float4 w0 = *reinterpret_cast<const float4*>(xp + 384);
            float4 w1 = *reinterpret_cast<const float4*>(xp + 388);
            XS[(cc + 0) * SR + r] = v0.x - w0.x;
            XS[(cc + 1) * SR + r] = v0.y - w0.y;
            XS[(cc + 2) * SR + r] = v0.z - w0.z;
            XS[(cc + 3) * SR + r] = v0.w - w0.w;
            XS[(cc + 4) * SR + r] = v1.x - w1.x;
            XS[(cc + 5) * SR + r] = v1.y - w1.y;
            XS[(cc + 6) * SR + r] = v1.z - w1.z;
            XS[(cc + 7) * SR + r] = v1.w - w1.w;
        }
        for (int idx = tid; idx < 64 * 20; idx += THREADS) {
            int k = idx / 20, c4 = (idx - k * 20) * 4;
            *reinterpret_cast<float4*>(&BS[k * BSS + c4]) =
                *reinterpret_cast<const float4*>(&g_B2[(kb + k) * NFP + c4]);
        }
        __syncthreads();
        const int k0 = s * 32;
        #pragma unroll 4
        for (int kt = 0; kt < 32; kt++) {
            int kk = k0 + kt;
            float4 av = *reinterpret_cast<const float4*>(&XS[kk * SR + r4]);
            ulonglong2 bq = *reinterpret_cast<const ulonglong2*>(&BS[kk * BSS + tc16 * 4]);
            float b4 = BS[kk * BSS + 64 + tc16];
            float a[4] = {av.x, av.y, av.z, av.w};
            #pragma unroll
            for (int j = 0; j < 4; j++) {
                u64 a2 = bcast2(a[j]);
                ffma2(acc1p[j][0], a2, bq.x);
                ffma2(acc1p[j][1], a2, bq.y);
                acc1s[j] = fmaf(a[j], b4, acc1s[j]);
            }
        }
    }
    {
        float* af = reinterpret_cast<float*>(acc1p);   // af[j*4 + l]
        #pragma unroll
        for (int i = 0; i < 16; i++)
            af[i] += __shfl_xor_sync(0xffffffffu, af[i], 16);
        #pragma unroll
        for (int j = 0; j < 4; j++)
            acc1s[j] += __shfl_xor_sync(0xffffffffu, acc1s[j], 16);
        if (s == 0) {
            #pragma unroll
            for (int l = 0; l < 4; l++) {
                int c = tc16 * 4 + l;
                *reinterpret_cast<float4*>(&XIN[c * SR + r4]) =
                    make_float4(af[l], af[4 + l], af[8 + l], af[12 + l]);
            }
            int c = 64 + tc16;
            if (c < NF)
                *reinterpret_cast<float4*>(&XIN[c * SR + r4]) =
                    make_float4(acc1s[0], acc1s[1], acc1s[2], acc1s[3]);
        }
    }

    // ===== Phase 2: two MLPs =====
    float zmu[4][5];
    #pragma unroll 1
    for (int p = 0; p < 2; p++) {
        const float* b1 = p ? sg_b1 : mu_b1;
        const float* gp = p ? sg_g : mu_g;
        const float* bp = p ? sg_beta : mu_beta;
        const float* b2 = p ? sg_b2 : mu_b2;
        const float* w1t = g_W1T[p];
        const float* w2t = g_W2T[p];

        __syncthreads();
        for (int idx = tid; idx < NF * 64; idx += THREADS) {
            int i = idx >> 6, j4 = (idx & 63) * 4;
            *reinterpret_cast<float4*>(&WB[i * W1S + j4]) =
                *reinterpret_cast<const float4*>(&w1t[i * HID + j4]);
        }
        __syncthreads();

        // GEMM1: H[64][256] = XIN @ W1^T — 8-row warp tiles, split-k
        const int c0 = ch * 128 + tc16 * 8;
        u64 accp[8][4];
        #pragma unroll
        for (int r = 0; r < 8; r++)
            #pragma unroll
            for (int q = 0; q < 4; q++) accp[r][q] = 0;
        const int i0 = s * 38;
        #pragma unroll 2
        for (int it = 0; it < 38; it++) {
            int i = i0 + it;
            float4 a0 = *reinterpret_cast<const float4*>(&XIN[i * SR + r8]);
            float4 a1 = *reinterpret_cast<const float4*>(&XIN[i * SR + r8 + 4]);
            const float* wrow = &WB[i * W1S + c0];
            ulonglong2 bq0 = *reinterpret_cast<const ulonglong2*>(wrow);
            ulonglong2 bq1 = *reinterpret_cast<const ulonglong2*>(wrow + 4);
            float a[8] = {a0.x, a0.y, a0.z, a0.w, a1.x, a1.y, a1.z, a1.w};
            #pragma unroll
            for (int r = 0; r < 8; r++) {
                u64 a2 = bcast2(a[r]);
                ffma2(accp[r][0], a2, bq0.x);
                ffma2(accp[r][1], a2, bq0.y);
                ffma2(accp[r][2], a2, bq1.x);
                ffma2(accp[r][3], a2, bq1.y);
            }
        }
        float* af = reinterpret_cast<float*>(accp);    // af[r*8 + c]
        #pragma unroll
        for (int i = 0; i < 64; i++)
            af[i] += __shfl_xor_sync(0xffffffffu, af[i], 16);

        // bias + per-warp partial LN stats
        {
            float4 q0 = __ldg(reinterpret_cast<const float4*>(&b1[c0]));
            float4 q1 = __ldg(reinterpret_cast<const float4*>(&b1[c0 + 4]));
            float bb[8] = {q0.x, q0.y, q0.z, q0.w, q1.x, q1.y, q1.z, q1.w};
            float sv[8], sq[8];
            #pragma unroll
            for (int r = 0; r < 8; r++) {
                sv[r] = 0.f; sq[r] = 0.f;
                #pragma unroll
                for (int c = 0; c < 8; c++) {
                    float v = af[r * 8 + c] + bb[c];
                    af[r * 8 + c] = v;
                    sv[r] += v;
                    sq[r] = fmaf(v, v, sq[r]);
                }
            }
            #pragma unroll
            for (int o = 1; o <= 8; o <<= 1) {
                #pragma unroll
                for (int r = 0; r < 8; r++) {
                    sv[r] += __shfl_xor_sync(0xffffffffu, sv[r], o);
                    sq[r] += __shfl_xor_sync(0xffffffffu, sq[r], o);
                }
            }
            if (lane == 0) {
                #pragma unroll
                for (int r = 0; r < 8; r++)
                    *reinterpret_cast<float2*>(&LNS[(r8 + r) * 4 + ch * 2]) =
                        make_float2(sv[r], sq[r]);
            }
        }
        __syncthreads();
        {
            float4 g0 = __ldg(reinterpret_cast<const float4*>(&gp[c0]));
            float4 g1 = __ldg(reinterpret_cast<const float4*>(&gp[c0 + 4]));
            float4 e0 = __ldg(reinterpret_cast<const float4*>(&bp[c0]));
            float4 e1 = __ldg(reinterpret_cast<const float4*>(&bp[c0 + 4]));
            float gg[8] = {g0.x, g0.y, g0.z, g0.w, g1.x, g1.y, g1.z, g1.w};
            float bt[8] = {e0.x, e0.y, e0.z, e0.w, e1.x, e1.y, e1.z, e1.w};
            #pragma unroll
            for (int r = 0; r < 8; r++) {
                float4 st = *reinterpret_cast<const float4*>(&LNS[(r8 + r) * 4]);
                float mean = (st.x + st.z) * (1.f / HID);
                float inv  = rsqrtf((st.y + st.w) * (1.f / HID) - mean * mean + 1e-5f);
                #pragma unroll
                for (int c = 0; c < 8; c++) {
                    float hn = (af[r * 8 + c] - mean) * inv * gg[c] + bt[c];
                    af[r * 8 + c] = 0.5f * hn * (1.f + erff(hn * 0.70710678118654752f));
                }
            }
        }
        if (s == 0) {
            #pragma unroll
            for (int c = 0; c < 8; c++) {
                *reinterpret_cast<float4*>(&HT[(c0 + c) * SR + r8]) =
                    make_float4(af[c], af[8 + c], af[16 + c], af[24 + c]);
                *reinterpret_cast<float4*>(&HT[(c0 + c) * SR + r8 + 4]) =
                    make_float4(af[32 + c], af[40 + c], af[48 + c], af[56 + c]);
            }
        }
        __syncthreads();

        for (int idx = tid; idx < HID * 20; idx += THREADS) {
            int k = idx / 20, c4 = (idx - k * 20) * 4;
            *reinterpret_cast<float4*>(&WB[k * W2S + c4]) =
                *reinterpret_cast<const float4*>(&w2t[k * NFP + c4]);
        }
        __syncthreads();

        // GEMM2: Z[64][80] = gelu(H) @ W2^T (split-k)
        u64 acc2p[4][2];
        float acc2s[4];
        #pragma unroll
        for (int j = 0; j < 4; j++) { acc2p[j][0] = 0; acc2p[j][1] = 0; acc2s[j] = 0.f; }
        const int kbase = s * 128;
        #pragma unroll 4
        for (int kt = 0; kt < 128; kt++) {
            int k = kbase + kt;
            float4 av = *reinterpret_cast<const float4*>(&HT[k * SR + r4]);
            ulonglong2 bq = *reinterpret_cast<const ulonglong2*>(&WB[k * W2S + tc16 * 4]);
            float b4 = WB[k * W2S + 64 + tc16];
            float a[4] = {av.x, av.y, av.z, av.w};
            #pragma unroll
            for (int j = 0; j < 4; j++) {
                u64 a2 = bcast2(a[j]);
                ffma2(acc2p[j][0], a2, bq.x);
                ffma2(acc2p[j][1], a2, bq.y);
                acc2s[j] = fmaf(a[j], b4, acc2s[j]);
            }
        }
        float* af2 = reinterpret_cast<float*>(acc2p);  // af2[j*4 + l]
        #pragma unroll
        for (int i = 0; i < 16; i++)
            af2[i] += __shfl_xor_sync(0xffffffffu, af2[i], 16);
        #pragma unroll
        for (int j = 0; j < 4; j++)
            acc2s[j] += __shfl_xor_sync(0xffffffffu, acc2s[j], 16);

        float4 b2v = __ldg(reinterpret_cast<const float4*>(&b2[tc16 * 4]));
        float  b2s = (tc16 < 12) ? __ldg(&b2[64 + tc16]) : 0.f;
        float bb2[5] = {b2v.x, b2v.y, b2v.z, b2v.w, b2s};
        if (p == 0) {
            #pragma unroll
            for (int j = 0; j < 4; j++) {
                #pragma unroll
                for (int l = 0; l < 4; l++)
                    zmu[j][l] = af2[j * 4 + l] + bb2[l];
                zmu[j][4] = acc2s[j] + bb2[4];
            }
        } else if (s == 0) {
            float z[4][5];
            #pragma unroll
            for (int j = 0; j < 4; j++) {
                int row = row0 + r4 + j;
                float4 ev = __ldg(reinterpret_cast<const float4*>(&eps[(size_t)row * NF + tc16 * 4]));
                float ee[5] = {ev.x, ev.y, ev.z, ev.w,
                               (tc16 < 12) ? __ldg(&eps[(size_t)row * NF + 64 + tc16]) : 0.f};
                #pragma unroll
                for (int l = 0; l < 4; l++)
                    z[j][l] = fmaf(ee[l], af2[j * 4 + l] + bb2[l], zmu[j][l]);
                z[j][4] = fmaf(ee[4], acc2s[j] + bb2[4], zmu[j][4]);
            }
            #pragma unroll
            for (int l = 0; l < 5; l++) {
                int c = (l < 4) ? tc16 * 4 + l : 64 + tc16;
                if (c < NF) {
                    float4 v = make_float4(z[0][l], z[1][l], z[2][l], z[3][l]);
                    *reinterpret_cast<float4*>(&ZS[c * SR + r4]) = v;
                }
            }
        }
    }

    // ===== Phase 3: W[64][384] = Z @ C2; out via i^q symmetry (split-k) =====
    const int cc0 = ch * 64 + tc16 * 4;
    for (int nc = 0; nc < KFOLD; nc += 128) {
        __syncthreads();
        for (int idx = tid; idx < NF * 32; idx += THREADS) {
            int k = idx >> 5, c4 = (idx & 31) * 4;
            *reinterpret_cast<float4*>(&CS[k * CSS + c4]) =
                *reinterpret_cast<const float4*>(&g_C2[k * KFOLD + nc + c4]);
        }
        __syncthreads();
        u64 acc3p[8][2];
        #pragma unroll
        for (int r = 0; r < 8; r++) { acc3p[r][0] = 0; acc3p[r][1] = 0; }
        const int kb3 = s * 38;
        #pragma unroll 2
        for (int kt = 0; kt < 38; kt++) {
            int k = kb3 + kt;
            float4 a0 = *reinterpret_cast<const float4*>(&ZS[k * SR + r8]);
            float4 a1 = *reinterpret_cast<const float4*>(&ZS[k * SR + r8 + 4]);
            ulonglong2 bq = *reinterpret_cast<const ulonglong2*>(&CS[k * CSS + cc0]);
            float a[8] = {a0.x, a0.y, a0.z, a0.w, a1.x, a1.y, a1.z, a1.w};
            #pragma unroll
            for (int r = 0; r < 8; r++) {
                u64 a2 = bcast2(a[r]);
                ffma2(acc3p[r][0], a2, bq.x);
                ffma2(acc3p[r][1], a2, bq.y);
            }
        }
        float* af3 = reinterpret_cast<float*>(acc3p);  // af3[r*4 + l]
        #pragma unroll
        for (int i = 0; i < 32; i++)
            af3[i] += __shfl_xor_sync(0xffffffffu, af3[i], 16);
        if (s == 0) {
            int c = nc + cc0;
            float sgn = (c < 192) ? 1.f : -1.f;    // Wre: (+, -) ; Wim: (-, +)
            #pragma unroll
            for (int r = 0; r < 8; r++) {
                size_t base = (size_t)(row0 + r8 + r) * IN_DIM;
                float4 v = make_float4(sgn * af3[r * 4 + 0], sgn * af3[r * 4 + 1],
                                       sgn * af3[r * 4 + 2], sgn * af3[r * 4 + 3]);
                *reinterpret_cast<float4*>(&out[base + c]) = v;
                *reinterpret_cast<float4*>(&out[base + c + 384]) =
                    make_float4(-v.x, -v.y, -v.z, -v.w);
            }
        }
    }
}

extern "C" void kernel_launch(void* const* d_in, const int* in_sizes, int n_in,
                              void* d_out, int out_size) {
    const float* x       = (const float*)d_in[0];
    const float* eps     = (const float*)d_in[1];
    const int*   indices = (const int*)  d_in[2];
    const float* mu_w1   = (const float*)d_in[3];
    const float* mu_b1   = (const float*)d_in[4];
    const float* mu_g    = (const float*)d_in[5];
    const float* mu_beta = (const float*)d_in[6];
    const float* mu_w2   = (const float*)d_in[7];
    const float* mu_b2   = (const float*)d_in[8];
    const float* sg_w1   = (const float*)d_in[9];
    const float* sg_b1   = (const float*)d_in[10];
    const float* sg_g    = (const float*)d_in[11];
    const float* sg_beta = (const float*)d_in[12];
    const float* sg_w2   = (const float*)d_in[13];
    const float* sg_b2   = (const float*)d_in[14];
    float* out = (float*)d_out;

    int n_rows = in_sizes[0] / IN_DIM;   // 32768

    cudaFuncSetAttribute(fused_kernel,
                         cudaFuncAttributeMaxDynamicSharedMemorySize, SMEM_BYTES);

    int pre_total = KFOLD * NFP + NF * KFOLD + 2 * NF * HID + 2 * HID * NFP;
    precompute_all<<<(pre_total + 255) / 256, 256>>>(indices, mu_w1, sg_w1, mu_w2, sg_w2);

    fused_kernel<<<n_rows / ROWS, THREADS, SMEM_BYTES>>>(
        x, eps,
        mu_b1, mu_g, mu_beta, mu_b2,
        sg_b1, sg_g, sg_beta, sg_b2,
        out);
}